// round 1
// baseline (speedup 1.0000x reference)
#include <cuda_runtime.h>
#include <math.h>

// ---------------------------------------------------------------------------
// Problem constants
// ---------------------------------------------------------------------------
#define Bn   4
#define Cc   192
#define C2   384
#define Hh   96
#define Ww   96
#define HW   (Hh*Ww)          // 9216
#define NH   8
#define HD   24               // C/NH
#define Gg   8
#define CG   24               // C/G

// scratch offsets (floats)
#define OFF_QKV1  0ul
#define OFF_QKV   14155776ul
#define OFF_CAT   28311552ul
#define OFF_SIG   42467328ul
#define OFF_SC    56623104ul
#define OFF_POOL  70778880ul   // 4*384*48*48 = 3538944
#define OFF_K2    74317824ul   // 4*384*46*46 = 3250176
#define OFF_OFF   77568000ul   // 4*18*9216   = 663552
#define OFF_FEAT  78231552ul   // 4*192*9216  = 7077888
#define OFF_K     85309440ul
#define OFF_AO    92387328ul
#define OFF_QN    99465216ul   // 768
#define OFF_KN    99465984ul   // 768
#define OFF_ATTN  99466752ul   // 4*8*24*24 = 18432
#define SCRATCH_TOTAL 99485184ul

__device__ float g_scratch[SCRATCH_TOTAL];

// ---------------------------------------------------------------------------
// Tiled implicit-GEMM conv: Y[b][m][oy][ox] = sum_{ic,ky,kx} W[m][ic][ky][kx]*X[b][ic][iy][ix]
// KS = 1 or 3.  Optional bias add, relu on input, elementwise multiply epilogue.
// BM=BN=64, BK=16, 256 threads, 4x4 per thread. Requires K % 16 == 0.
// ---------------------------------------------------------------------------
#define BM 64
#define BN 64
#define BK 16

template<int KS>
__global__ __launch_bounds__(256)
void conv_gemm(const float* __restrict__ W,
               const float* __restrict__ X,
               float* __restrict__ Y,
               const float* __restrict__ bias,
               const float* __restrict__ mul,
               int M, int Cin, int IH, int IW,
               int OH, int OW, int pad, int relu_in)
{
    const int N = OH * OW;
    const int K = Cin * KS * KS;
    const int bz = blockIdx.z;
    const int m0 = blockIdx.y * BM;
    const int n0 = blockIdx.x * BN;

    __shared__ float As[BK][BM];
    __shared__ float Bs[BK][BN + 4];

    const int tid = threadIdx.x;
    const int tm  = tid >> 4;     // 0..15
    const int tn  = tid & 15;     // 0..15

    float acc[4][4] = {};

    const float* Xb = X + (size_t)bz * Cin * IH * IW;

    for (int k0 = 0; k0 < K; k0 += BK) {
        // ---- load A tile (weights): 4 consecutive k per thread -----------
        {
            int m  = tid >> 2;            // 0..63
            int kk = (tid & 3) * 4;       // 0,4,8,12
            int gm = m0 + m;
            float4 a = make_float4(0.f, 0.f, 0.f, 0.f);
            if (gm < M)
                a = *reinterpret_cast<const float4*>(W + (size_t)gm * K + k0 + kk);
            As[kk + 0][m] = a.x;
            As[kk + 1][m] = a.y;
            As[kk + 2][m] = a.z;
            As[kk + 3][m] = a.w;
        }
        // ---- load B tile (gathered input) ---------------------------------
        #pragma unroll
        for (int r = 0; r < 4; ++r) {
            int kk = r * 4 + (tid >> 6);
            int n  = tid & 63;
            int gk = k0 + kk;
            int gn = n0 + n;
            float v = 0.f;
            if (gn < N) {
                if (KS == 1) {
                    v = Xb[(size_t)gk * N + gn];
                } else {
                    int ic = gk / 9;
                    int t  = gk - ic * 9;
                    int oy = gn / OW, ox = gn - oy * OW;
                    int iy = oy + t / 3 - pad;
                    int ix = ox + (t % 3) - pad;
                    if (iy >= 0 && iy < IH && ix >= 0 && ix < IW)
                        v = Xb[((size_t)ic * IH + iy) * IW + ix];
                }
                if (relu_in) v = fmaxf(v, 0.f);
            }
            Bs[kk][n] = v;
        }
        __syncthreads();

        #pragma unroll
        for (int kk = 0; kk < BK; ++kk) {
            float4 av = *reinterpret_cast<const float4*>(&As[kk][tm * 4]);
            float4 bv = *reinterpret_cast<const float4*>(&Bs[kk][tn * 4]);
            acc[0][0] += av.x * bv.x; acc[0][1] += av.x * bv.y;
            acc[0][2] += av.x * bv.z; acc[0][3] += av.x * bv.w;
            acc[1][0] += av.y * bv.x; acc[1][1] += av.y * bv.y;
            acc[1][2] += av.y * bv.z; acc[1][3] += av.y * bv.w;
            acc[2][0] += av.z * bv.x; acc[2][1] += av.z * bv.y;
            acc[2][2] += av.z * bv.z; acc[2][3] += av.z * bv.w;
            acc[3][0] += av.w * bv.x; acc[3][1] += av.w * bv.y;
            acc[3][2] += av.w * bv.z; acc[3][3] += av.w * bv.w;
        }
        __syncthreads();
    }

    #pragma unroll
    for (int i = 0; i < 4; ++i) {
        int m = m0 + tm * 4 + i;
        if (m >= M) continue;
        #pragma unroll
        for (int j = 0; j < 4; ++j) {
            int n = n0 + tn * 4 + j;
            if (n >= N) continue;
            float v = acc[i][j];
            if (bias) v += bias[m];
            size_t idx = ((size_t)bz * M + m) * N + n;
            if (mul) v *= mul[idx];
            Y[idx] = v;
        }
    }
}

// ---------------------------------------------------------------------------
// grouped 3x3 conv with groups=192 on 384 channels (2 in / 2 out per group)
// ---------------------------------------------------------------------------
__global__ void dwconv_kernel(const float* __restrict__ X,
                              const float* __restrict__ W,
                              float* __restrict__ Y)
{
    int idx = blockIdx.x * blockDim.x + threadIdx.x;
    if (idx >= Bn * C2 * HW) return;
    int p  = idx % HW;
    int oc = (idx / HW) % C2;
    int b  = idx / (HW * C2);
    int y = p / Ww, x = p % Ww;
    int g = oc >> 1;
    const float* w = W + (size_t)oc * 18;
    float s = 0.f;
    #pragma unroll
    for (int i = 0; i < 2; ++i) {
        const float* xp = X + ((size_t)b * C2 + 2 * g + i) * HW;
        #pragma unroll
        for (int ky = 0; ky < 3; ++ky) {
            int iy = y + ky - 1;
            if (iy < 0 || iy >= Hh) continue;
            #pragma unroll
            for (int kx = 0; kx < 3; ++kx) {
                int ix = x + kx - 1;
                if (ix < 0 || ix >= Ww) continue;
                s += w[i * 9 + ky * 3 + kx] * xp[iy * Ww + ix];
            }
        }
    }
    Y[idx] = s;
}

// cat = [q ; y]
__global__ void cat_kernel(const float* __restrict__ QKV,
                           const float* __restrict__ Yin,
                           float* __restrict__ CAT)
{
    int idx = blockIdx.x * blockDim.x + threadIdx.x;
    if (idx >= Bn * C2 * HW) return;
    int p = idx % HW;
    int c = (idx / HW) % C2;
    int b = idx / (HW * C2);
    float v;
    if (c < Cc) v = QKV[((size_t)b * C2 + c) * HW + p];
    else        v = Yin[((size_t)b * Cc + (c - Cc)) * HW + p];
    CAT[idx] = v;
}

// 2x2 avg pool, 96 -> 48
__global__ void pool_kernel(const float* __restrict__ X, float* __restrict__ Y)
{
    int idx = blockIdx.x * blockDim.x + threadIdx.x;
    const int OHW = 48 * 48;
    if (idx >= Bn * C2 * OHW) return;
    int p  = idx % OHW;
    int bc = idx / OHW;
    int y = p / 48, x = p % 48;
    const float* xp = X + (size_t)bc * HW;
    float s = xp[(2 * y) * Ww + 2 * x] + xp[(2 * y) * Ww + 2 * x + 1]
            + xp[(2 * y + 1) * Ww + 2 * x] + xp[(2 * y + 1) * Ww + 2 * x + 1];
    Y[idx] = s * 0.25f;
}

// sig = sigmoid(cat + nearest_resize(k2out 46x46 -> 96x96))
__global__ void sig_kernel(const float* __restrict__ CAT,
                           const float* __restrict__ K2,
                           float* __restrict__ SIG)
{
    int idx = blockIdx.x * blockDim.x + threadIdx.x;
    if (idx >= Bn * C2 * HW) return;
    int p  = idx % HW;
    int bc = idx / HW;
    int y = p / Ww, x = p % Ww;
    int iy = (y * 46) / 96;
    int ix = (x * 46) / 96;
    float s = CAT[idx] + K2[(size_t)bc * (46 * 46) + iy * 46 + ix];
    SIG[idx] = 1.f / (1.f + expf(-s));
}

// ---------------------------------------------------------------------------
// fused deformable conv (groups=8, cg=24, 3x3, offsets shared over channels)
// ---------------------------------------------------------------------------
__global__ __launch_bounds__(128)
void deform_kernel(const float* __restrict__ Q,     // [B][384][HW], q = ch 0..191
                   const float* __restrict__ OFF,   // [B][18][HW]
                   const float* __restrict__ W,     // [192][24][3][3]
                   const float* __restrict__ Bias,  // [192]
                   float* __restrict__ Y)           // [B][192][HW]
{
    __shared__ float ws[24 * 216];   // ws[o*216 + i*9 + t]
    const int g = blockIdx.y;
    const int b = blockIdx.z;
    const int tid = threadIdx.x;

    for (int e = tid; e < 24 * 216; e += 128) {
        int o = e / 216, r = e - o * 216;
        ws[e] = W[(size_t)(g * CG + o) * 216 + r];   // [oc][i][ky][kx] contiguous = [oc][i*9+t]
    }
    __syncthreads();

    int p = blockIdx.x * 128 + tid;
    int y = p / Ww, x = p % Ww;
    const float* offb = OFF + (size_t)b * 18 * HW;

    float acc[24];
    #pragma unroll
    for (int o = 0; o < 24; ++o) acc[o] = Bias[g * CG + o];

    const float* qc = Q + ((size_t)b * C2 + g * CG) * HW;

    for (int t = 0; t < 9; ++t) {
        float dy = offb[(size_t)(2 * t) * HW + p];
        float dx = offb[(size_t)(2 * t + 1) * HW + p];
        float m  = 1.f / (1.f + expf(-offb[(size_t)t * HW + p]));
        float py = dy + (float)(y - 1 + t / 3);
        float px = dx + (float)(x - 1 + t % 3);
        float y0f = floorf(py), x0f = floorf(px);
        int   y0 = (int)y0f,    x0 = (int)x0f;
        float fy = py - y0f,    fx = px - x0f;
        float w00 = (1.f - fy) * (1.f - fx);
        float w01 = (1.f - fy) * fx;
        float w10 = fy * (1.f - fx);
        float w11 = fy * fx;
        bool vy0 = (y0 >= 0 && y0 <= Hh - 1), vy1 = (y0 + 1 >= 0 && y0 + 1 <= Hh - 1);
        bool vx0 = (x0 >= 0 && x0 <= Ww - 1), vx1 = (x0 + 1 >= 0 && x0 + 1 <= Ww - 1);
        int cy0 = min(max(y0, 0), Hh - 1),     cy1 = min(max(y0 + 1, 0), Hh - 1);
        int cx0 = min(max(x0, 0), Ww - 1),     cx1 = min(max(x0 + 1, 0), Ww - 1);
        int i00 = cy0 * Ww + cx0, i01 = cy0 * Ww + cx1;
        int i10 = cy1 * Ww + cx0, i11 = cy1 * Ww + cx1;
        w00 = (vy0 && vx0) ? w00 * m : 0.f;
        w01 = (vy0 && vx1) ? w01 * m : 0.f;
        w10 = (vy1 && vx0) ? w10 * m : 0.f;
        w11 = (vy1 && vx1) ? w11 * m : 0.f;

        #pragma unroll
        for (int i = 0; i < 24; ++i) {
            const float* qp = qc + (size_t)i * HW;
            float val = w00 * qp[i00] + w01 * qp[i01] + w10 * qp[i10] + w11 * qp[i11];
            const float* wr = &ws[i * 9 + t];
            #pragma unroll
            for (int o = 0; o < 24; ++o) acc[o] += val * wr[o * 216];
        }
    }
    #pragma unroll
    for (int o = 0; o < 24; ++o)
        Y[((size_t)b * Cc + g * CG + o) * HW + p] = acc[o];
}

// ---------------------------------------------------------------------------
// row L2 norms for q (inside QKV buffer) and k
// ---------------------------------------------------------------------------
__global__ void rownorm_kernel(const float* __restrict__ QKV,
                               const float* __restrict__ Kb,
                               float* __restrict__ QN,
                               float* __restrict__ KN)
{
    int row   = blockIdx.x;            // 0..1535
    int which = row / (Bn * Cc);
    row %= (Bn * Cc);
    int b = row / Cc, c = row % Cc;
    const float* src = which ? (Kb + ((size_t)b * Cc + c) * HW)
                             : (QKV + ((size_t)b * C2 + c) * HW);
    float s = 0.f;
    for (int n = threadIdx.x; n < HW; n += 256) {
        float v = src[n];
        s += v * v;
    }
    __shared__ float sm[256];
    sm[threadIdx.x] = s;
    __syncthreads();
    for (int d = 128; d > 0; d >>= 1) {
        if (threadIdx.x < d) sm[threadIdx.x] += sm[threadIdx.x + d];
        __syncthreads();
    }
    if (threadIdx.x == 0) {
        float nrm = fmaxf(sqrtf(sm[0]), 1e-12f);
        (which ? KN : QN)[b * Cc + c] = nrm;
    }
}

// ---------------------------------------------------------------------------
// attention logits + softmax.  block = (b, h, i); computes row i of 24x24.
// ---------------------------------------------------------------------------
__global__ void attn_kernel(const float* __restrict__ QKV,
                            const float* __restrict__ Kb,
                            const float* __restrict__ QN,
                            const float* __restrict__ KN,
                            const float* __restrict__ TEMP,
                            float* __restrict__ ATTN)
{
    int blk = blockIdx.x;
    int b = blk / (NH * HD);
    int h = (blk / HD) % NH;
    int i = blk % HD;
    const float* qrow  = QKV + ((size_t)b * C2 + h * HD + i) * HW;
    const float* krows = Kb  + ((size_t)b * Cc + h * HD) * HW;

    float acc[HD] = {};
    for (int n = threadIdx.x; n < HW; n += 256) {
        float qv = qrow[n];
        #pragma unroll
        for (int j = 0; j < HD; ++j)
            acc[j] += qv * krows[(size_t)j * HW + n];
    }
    __shared__ float red[HD];
    if (threadIdx.x < HD) red[threadIdx.x] = 0.f;
    __syncthreads();
    int lane = threadIdx.x & 31;
    #pragma unroll
    for (int j = 0; j < HD; ++j) {
        float v = acc[j];
        for (int o = 16; o > 0; o >>= 1) v += __shfl_down_sync(0xffffffffu, v, o);
        if (lane == 0) atomicAdd(&red[j], v);
    }
    __syncthreads();
    if (threadIdx.x == 0) {
        float qn = QN[b * Cc + h * HD + i];
        float tp = TEMP[h];
        float s[HD];
        float mx = -1e30f;
        #pragma unroll
        for (int j = 0; j < HD; ++j) {
            s[j] = red[j] / (qn * KN[b * Cc + h * HD + j]) * tp;
            mx = fmaxf(mx, s[j]);
        }
        float sum = 0.f;
        #pragma unroll
        for (int j = 0; j < HD; ++j) { s[j] = expf(s[j] - mx); sum += s[j]; }
        float inv = 1.f / sum;
        #pragma unroll
        for (int j = 0; j < HD; ++j)
            ATTN[(((size_t)b * NH + h) * HD + i) * HD + j] = s[j] * inv;
    }
}

// out = attn @ v ;  v = QKV channels 192..383
__global__ void attnv_kernel(const float* __restrict__ ATTN,
                             const float* __restrict__ QKV,
                             float* __restrict__ AO)
{
    int h = blockIdx.y, b = blockIdx.z;
    int n = blockIdx.x * 256 + threadIdx.x;
    __shared__ float a_s[HD * HD];
    for (int e = threadIdx.x; e < HD * HD; e += 256)
        a_s[e] = ATTN[((size_t)b * NH + h) * HD * HD + e];
    __syncthreads();
    const float* vb = QKV + ((size_t)b * C2 + Cc + h * HD) * HW;
    float acc[HD] = {};
    #pragma unroll
    for (int j = 0; j < HD; ++j) {
        float vv = vb[(size_t)j * HW + n];
        #pragma unroll
        for (int i = 0; i < HD; ++i) acc[i] += a_s[i * HD + j] * vv;
    }
    #pragma unroll
    for (int i = 0; i < HD; ++i)
        AO[((size_t)b * Cc + h * HD + i) * HW + n] = acc[i];
}

// ---------------------------------------------------------------------------
// launcher
// ---------------------------------------------------------------------------
extern "C" void kernel_launch(void* const* d_in, const int* in_sizes, int n_in,
                              void* d_out, int out_size)
{
    const float* x           = (const float*)d_in[0];
    const float* y           = (const float*)d_in[1];
    const float* temperature = (const float*)d_in[2];
    const float* qkv_w       = (const float*)d_in[3];
    const float* qkv_conv_w  = (const float*)d_in[4];
    const float* proj_w      = (const float*)d_in[5];
    const float* k2_w        = (const float*)d_in[6];
    const float* k3_w        = (const float*)d_in[7];
    const float* k4_w        = (const float*)d_in[8];
    const float* deform_w    = (const float*)d_in[9];
    const float* deform_b    = (const float*)d_in[10];
    const float* pw_w        = (const float*)d_in[11];
    const float* pw_b        = (const float*)d_in[12];
    float* out = (float*)d_out;

    float* S = nullptr;
    cudaGetSymbolAddress((void**)&S, g_scratch);
    float* QKV1 = S + OFF_QKV1;
    float* QKV  = S + OFF_QKV;
    float* CAT  = S + OFF_CAT;
    float* SIG  = S + OFF_SIG;
    float* SC   = S + OFF_SC;
    float* POOL = S + OFF_POOL;
    float* K2   = S + OFF_K2;
    float* OFFb = S + OFF_OFF;
    float* FEAT = S + OFF_FEAT;
    float* Kb   = S + OFF_K;
    float* AO   = S + OFF_AO;
    float* QN   = S + OFF_QN;
    float* KN   = S + OFF_KN;
    float* ATTN = S + OFF_ATTN;

    const int NE = Bn * C2 * HW;            // 14155776

    // 1) qkv 1x1:  384 x (192) x 9216
    conv_gemm<1><<<dim3(HW / 64, C2 / 64, Bn), 256>>>(
        qkv_w, x, QKV1, nullptr, nullptr, C2, Cc, Hh, Ww, Hh, Ww, 0, 0);
    // 2) grouped 3x3 (groups=192)
    dwconv_kernel<<<(NE + 255) / 256, 256>>>(QKV1, qkv_conv_w, QKV);
    // 3) cat = [q ; y]
    cat_kernel<<<(NE + 255) / 256, 256>>>(QKV, y, CAT);
    // 4) avg pool 2x2
    pool_kernel<<<(Bn * C2 * 48 * 48 + 255) / 256, 256>>>(CAT, POOL);
    // 5) k2 conv 3x3 pad=0 : 48x48 -> 46x46
    conv_gemm<3><<<dim3((46 * 46 + 63) / 64, C2 / 64, Bn), 256>>>(
        k2_w, POOL, K2, nullptr, nullptr, C2, C2, 48, 48, 46, 46, 0, 0);
    // 6) sig = sigmoid(cat + upsample(k2))
    sig_kernel<<<(NE + 255) / 256, 256>>>(CAT, K2, SIG);
    // 7) sc = conv3x3(cat, k3, pad=1) * sig
    conv_gemm<3><<<dim3(HW / 64, C2 / 64, Bn), 256>>>(
        k3_w, CAT, SC, nullptr, SIG, C2, C2, Hh, Ww, Hh, Ww, 1, 0);
    // 8) offset = conv3x3(sc, k4, pad=1), M=18
    conv_gemm<3><<<dim3(HW / 64, 1, Bn), 256>>>(
        k4_w, SC, OFFb, nullptr, nullptr, 18, C2, Hh, Ww, Hh, Ww, 1, 0);
    // 9) deformable conv -> feat
    deform_kernel<<<dim3(HW / 128, Gg, Bn), 128>>>(QKV, OFFb, deform_w, deform_b, FEAT);
    // 10) k = 1x1(relu(feat)) + pw_b
    conv_gemm<1><<<dim3(HW / 64, Cc / 64, Bn), 256>>>(
        pw_w, FEAT, Kb, pw_b, nullptr, Cc, Cc, Hh, Ww, Hh, Ww, 0, 1);
    // 11) row norms for q, k
    rownorm_kernel<<<2 * Bn * Cc, 256>>>(QKV, Kb, QN, KN);
    // 12) attention logits + softmax (24x24 per head)
    attn_kernel<<<Bn * NH * HD, 256>>>(QKV, Kb, QN, KN, temperature, ATTN);
    // 13) out = attn @ v
    attnv_kernel<<<dim3(HW / 256, NH, Bn), 256>>>(ATTN, QKV, AO);
    // 14) final 1x1 proj -> d_out
    conv_gemm<1><<<dim3(HW / 64, Cc / 64, Bn), 256>>>(
        proj_w, AO, out, nullptr, nullptr, Cc, Cc, Hh, Ww, Hh, Ww, 0, 0);
}

// round 2
// speedup vs baseline: 1.7871x; 1.7871x over previous
#include <cuda_runtime.h>
#include <math.h>
#include <stdint.h>

// ---------------------------------------------------------------------------
// Problem constants
// ---------------------------------------------------------------------------
#define Bn   4
#define Cc   192
#define C2   384
#define Hh   96
#define Ww   96
#define HW   (Hh*Ww)          // 9216
#define NH   8
#define HD   24               // C/NH
#define Gg   8
#define CG   24               // C/G

// scratch offsets (floats)
#define OFF_QKV1  0ul
#define OFF_QKV   14155776ul
#define OFF_CAT   28311552ul
#define OFF_SIG   42467328ul
#define OFF_SC    56623104ul
#define OFF_POOL  70778880ul
#define OFF_K2    74317824ul
#define OFF_OFF   77568000ul
#define OFF_FEAT  78231552ul
#define OFF_K     85309440ul
#define OFF_AO    92387328ul
#define OFF_QN    99465216ul
#define OFF_KN    99465984ul
#define OFF_ATTN  99466752ul
#define SCRATCH_TOTAL 99485184ul

__device__ float g_scratch[SCRATCH_TOTAL];

// ---------------------------------------------------------------------------
// tf32 helpers
// ---------------------------------------------------------------------------
__device__ __forceinline__ float f2tf32(float x) {
    uint32_t u;
    asm("cvt.rna.tf32.f32 %0, %1;" : "=r"(u) : "f"(x));
    return __uint_as_float(u);
}

__device__ __forceinline__ void mma_16x8x8(float* c, const uint32_t* a,
                                           uint32_t b0, uint32_t b1) {
    asm volatile(
        "mma.sync.aligned.m16n8k8.row.col.f32.tf32.tf32.f32 "
        "{%0,%1,%2,%3}, {%4,%5,%6,%7}, {%8,%9}, {%0,%1,%2,%3};\n"
        : "+f"(c[0]), "+f"(c[1]), "+f"(c[2]), "+f"(c[3])
        : "r"(a[0]), "r"(a[1]), "r"(a[2]), "r"(a[3]), "r"(b0), "r"(b1));
}

// ---------------------------------------------------------------------------
// tf32 tensor-core implicit-GEMM conv.
// KS = 1 or 3.  FM = m16-frags per warp in M (4 -> BM=128, 1 -> BM=32).
// 256 threads = 8 warps (2 in M x 4 in N). BN=128, BK=16. K % 16 == 0.
// Epilogues: optional bias add (per out-channel), relu on input, elementwise
// multiply by `mul`.
// ---------------------------------------------------------------------------
template<int KS, int FM>
__global__ __launch_bounds__(256)
void conv_mma(const float* __restrict__ Wt,
              const float* __restrict__ X,
              float* __restrict__ Y,
              const float* __restrict__ bias,
              const float* __restrict__ mul,
              int M, int Cin, int IH, int IW,
              int OH, int OW, int pad, int relu_in)
{
    constexpr int BM   = 32 * FM;
    constexpr int BN   = 128;
    constexpr int BK   = 16;
    constexpr int ASTR = BM + 8;
    constexpr int BSTR = BN + 8;
    constexpr int AELE = BM * BK / 4;               // float4 elements of A tile
    constexpr int AITER = (AELE + 255) / 256;

    __shared__ float As[2][BK * ASTR];
    __shared__ float Bs[2][BK * BSTR];

    const int N  = OH * OW;
    const int K  = Cin * KS * KS;
    const int bz = blockIdx.z;
    const int m0 = blockIdx.y * BM;
    const int n0 = blockIdx.x * BN;

    const int tid  = threadIdx.x;
    const int wid  = tid >> 5;
    const int lane = tid & 31;
    const int wm   = wid & 1;          // 0..1
    const int wn   = wid >> 1;         // 0..3
    const int mbase = wm * (16 * FM);
    const int nbase = wn * 32;
    const int lg = lane >> 2;          // group id 0..7
    const int lt = lane & 3;           // thread-in-group 0..3

    const float* Xb = X + (size_t)bz * Cin * IH * IW;

    float acc[FM][4][4];
    #pragma unroll
    for (int f = 0; f < FM; ++f)
        #pragma unroll
        for (int nf = 0; nf < 4; ++nf)
            #pragma unroll
            for (int r = 0; r < 4; ++r) acc[f][nf][r] = 0.f;

    // --- B gather coordinates (fixed per thread) ---
    const int bn = tid & 127;
    const int gn = n0 + bn;
    const bool nvalid = gn < N;
    int oy = 0, ox = 0;
    if (KS == 3 && nvalid) { oy = gn / OW; ox = gn - oy * OW; }

    float4 aReg[AITER];
    float  bReg[8];

    auto ldA = [&](int k0) {
        #pragma unroll
        for (int r = 0; r < AITER; ++r) {
            int e = tid + r * 256;
            float4 v = make_float4(0.f, 0.f, 0.f, 0.f);
            if (AELE == 512 || e < AELE) {
                int m  = e >> 2;
                int kq = e & 3;
                int gm = m0 + m;
                if (gm < M)
                    v = *reinterpret_cast<const float4*>(Wt + (size_t)gm * K + k0 + kq * 4);
            }
            aReg[r] = v;
        }
    };
    auto stA = [&](int buf) {
        #pragma unroll
        for (int r = 0; r < AITER; ++r) {
            int e = tid + r * 256;
            if (AELE == 512 || e < AELE) {
                int m  = e >> 2;
                int kq = e & 3;
                float* p = &As[buf][(kq * 4) * ASTR + m];
                p[0 * ASTR] = f2tf32(aReg[r].x);
                p[1 * ASTR] = f2tf32(aReg[r].y);
                p[2 * ASTR] = f2tf32(aReg[r].z);
                p[3 * ASTR] = f2tf32(aReg[r].w);
            }
        }
    };
    auto ldB = [&](int k0) {
        #pragma unroll
        for (int r = 0; r < 8; ++r) {
            int k  = (tid >> 7) + 2 * r;
            int gk = k0 + k;
            float v = 0.f;
            if (nvalid) {
                if (KS == 1) {
                    v = Xb[(size_t)gk * N + gn];
                } else {
                    int ic = gk / 9;
                    int t  = gk - ic * 9;
                    int iy = oy + t / 3 - pad;
                    int ix = ox + (t % 3) - pad;
                    if (iy >= 0 && iy < IH && ix >= 0 && ix < IW)
                        v = Xb[((size_t)ic * IH + iy) * IW + ix];
                }
                if (relu_in) v = fmaxf(v, 0.f);
            }
            bReg[r] = v;
        }
    };
    auto stB = [&](int buf) {
        #pragma unroll
        for (int r = 0; r < 8; ++r) {
            int k = (tid >> 7) + 2 * r;
            Bs[buf][k * BSTR + bn] = f2tf32(bReg[r]);
        }
    };
    auto compute = [&](int buf) {
        #pragma unroll
        for (int ks = 0; ks < 2; ++ks) {
            const int kr = ks * 8 + lt;
            uint32_t a[FM][4];
            #pragma unroll
            for (int f = 0; f < FM; ++f) {
                int mr = mbase + f * 16 + lg;
                a[f][0] = __float_as_uint(As[buf][kr * ASTR + mr]);
                a[f][1] = __float_as_uint(As[buf][kr * ASTR + mr + 8]);
                a[f][2] = __float_as_uint(As[buf][(kr + 4) * ASTR + mr]);
                a[f][3] = __float_as_uint(As[buf][(kr + 4) * ASTR + mr + 8]);
            }
            #pragma unroll
            for (int nf = 0; nf < 4; ++nf) {
                int nc = nbase + nf * 8 + lg;
                uint32_t b0 = __float_as_uint(Bs[buf][kr * BSTR + nc]);
                uint32_t b1 = __float_as_uint(Bs[buf][(kr + 4) * BSTR + nc]);
                #pragma unroll
                for (int f = 0; f < FM; ++f)
                    mma_16x8x8(acc[f][nf], a[f], b0, b1);
            }
        }
    };

    const int kTiles = K / BK;
    ldA(0); ldB(0);
    stA(0); stB(0);
    __syncthreads();

    for (int t = 0; t < kTiles; ++t) {
        if (t + 1 < kTiles) { ldA((t + 1) * BK); ldB((t + 1) * BK); }
        compute(t & 1);
        if (t + 1 < kTiles) {
            stA((t + 1) & 1); stB((t + 1) & 1);
            __syncthreads();
        }
    }

    // ---- epilogue ----
    #pragma unroll
    for (int f = 0; f < FM; ++f) {
        int r0 = m0 + mbase + f * 16 + lg;
        #pragma unroll
        for (int nf = 0; nf < 4; ++nf) {
            int cb = n0 + nbase + nf * 8 + 2 * lt;
            #pragma unroll
            for (int rr = 0; rr < 2; ++rr) {
                int m = r0 + rr * 8;
                if (m >= M) continue;
                float bval = bias ? bias[m] : 0.f;
                #pragma unroll
                for (int cc = 0; cc < 2; ++cc) {
                    int n = cb + cc;
                    if (n >= N) continue;
                    float v = acc[f][nf][rr * 2 + cc] + bval;
                    size_t idx = ((size_t)bz * M + m) * N + n;
                    if (mul) v *= mul[idx];
                    Y[idx] = v;
                }
            }
        }
    }
}

// ---------------------------------------------------------------------------
// grouped 3x3 conv with groups=192 on 384 channels (2 in / 2 out per group)
// ---------------------------------------------------------------------------
__global__ void dwconv_kernel(const float* __restrict__ X,
                              const float* __restrict__ W,
                              float* __restrict__ Y)
{
    int idx = blockIdx.x * blockDim.x + threadIdx.x;
    if (idx >= Bn * C2 * HW) return;
    int p  = idx % HW;
    int oc = (idx / HW) % C2;
    int b  = idx / (HW * C2);
    int y = p / Ww, x = p % Ww;
    int g = oc >> 1;
    const float* w = W + (size_t)oc * 18;
    float s = 0.f;
    #pragma unroll
    for (int i = 0; i < 2; ++i) {
        const float* xp = X + ((size_t)b * C2 + 2 * g + i) * HW;
        #pragma unroll
        for (int ky = 0; ky < 3; ++ky) {
            int iy = y + ky - 1;
            if (iy < 0 || iy >= Hh) continue;
            #pragma unroll
            for (int kx = 0; kx < 3; ++kx) {
                int ix = x + kx - 1;
                if (ix < 0 || ix >= Ww) continue;
                s += w[i * 9 + ky * 3 + kx] * xp[iy * Ww + ix];
            }
        }
    }
    Y[idx] = s;
}

// cat = [q ; y]
__global__ void cat_kernel(const float* __restrict__ QKV,
                           const float* __restrict__ Yin,
                           float* __restrict__ CAT)
{
    int idx = blockIdx.x * blockDim.x + threadIdx.x;
    if (idx >= Bn * C2 * HW) return;
    int p = idx % HW;
    int c = (idx / HW) % C2;
    int b = idx / (HW * C2);
    float v;
    if (c < Cc) v = QKV[((size_t)b * C2 + c) * HW + p];
    else        v = Yin[((size_t)b * Cc + (c - Cc)) * HW + p];
    CAT[idx] = v;
}

// 2x2 avg pool, 96 -> 48
__global__ void pool_kernel(const float* __restrict__ X, float* __restrict__ Y)
{
    int idx = blockIdx.x * blockDim.x + threadIdx.x;
    const int OHW = 48 * 48;
    if (idx >= Bn * C2 * OHW) return;
    int p  = idx % OHW;
    int bc = idx / OHW;
    int y = p / 48, x = p % 48;
    const float* xp = X + (size_t)bc * HW;
    float s = xp[(2 * y) * Ww + 2 * x] + xp[(2 * y) * Ww + 2 * x + 1]
            + xp[(2 * y + 1) * Ww + 2 * x] + xp[(2 * y + 1) * Ww + 2 * x + 1];
    Y[idx] = s * 0.25f;
}

// sig = sigmoid(cat + nearest_resize(k2out 46x46 -> 96x96))
__global__ void sig_kernel(const float* __restrict__ CAT,
                           const float* __restrict__ K2,
                           float* __restrict__ SIG)
{
    int idx = blockIdx.x * blockDim.x + threadIdx.x;
    if (idx >= Bn * C2 * HW) return;
    int p  = idx % HW;
    int bc = idx / HW;
    int y = p / Ww, x = p % Ww;
    int iy = (y * 46) / 96;
    int ix = (x * 46) / 96;
    float s = CAT[idx] + K2[(size_t)bc * (46 * 46) + iy * 46 + ix];
    SIG[idx] = 1.f / (1.f + expf(-s));
}

// ---------------------------------------------------------------------------
// fused deformable conv (groups=8, cg=24, 3x3, offsets shared over channels)
// ---------------------------------------------------------------------------
__global__ __launch_bounds__(128)
void deform_kernel(const float* __restrict__ Q,     // [B][384][HW], q = ch 0..191
                   const float* __restrict__ OFF,   // [B][18][HW]
                   const float* __restrict__ W,     // [192][24][3][3]
                   const float* __restrict__ Bias,  // [192]
                   float* __restrict__ Y)           // [B][192][HW]
{
    __shared__ float ws[24 * 216];
    const int g = blockIdx.y;
    const int b = blockIdx.z;
    const int tid = threadIdx.x;

    for (int e = tid; e < 24 * 216; e += 128) {
        int o = e / 216, r = e - o * 216;
        ws[e] = W[(size_t)(g * CG + o) * 216 + r];
    }
    __syncthreads();

    int p = blockIdx.x * 128 + tid;
    int y = p / Ww, x = p % Ww;
    const float* offb = OFF + (size_t)b * 18 * HW;

    float acc[24];
    #pragma unroll
    for (int o = 0; o < 24; ++o) acc[o] = Bias[g * CG + o];

    const float* qc = Q + ((size_t)b * C2 + g * CG) * HW;

    for (int t = 0; t < 9; ++t) {
        float dy = offb[(size_t)(2 * t) * HW + p];
        float dx = offb[(size_t)(2 * t + 1) * HW + p];
        float m  = 1.f / (1.f + expf(-offb[(size_t)t * HW + p]));
        float py = dy + (float)(y - 1 + t / 3);
        float px = dx + (float)(x - 1 + t % 3);
        float y0f = floorf(py), x0f = floorf(px);
        int   y0 = (int)y0f,    x0 = (int)x0f;
        float fy = py - y0f,    fx = px - x0f;
        float w00 = (1.f - fy) * (1.f - fx);
        float w01 = (1.f - fy) * fx;
        float w10 = fy * (1.f - fx);
        float w11 = fy * fx;
        bool vy0 = (y0 >= 0 && y0 <= Hh - 1), vy1 = (y0 + 1 >= 0 && y0 + 1 <= Hh - 1);
        bool vx0 = (x0 >= 0 && x0 <= Ww - 1), vx1 = (x0 + 1 >= 0 && x0 + 1 <= Ww - 1);
        int cy0 = min(max(y0, 0), Hh - 1),     cy1 = min(max(y0 + 1, 0), Hh - 1);
        int cx0 = min(max(x0, 0), Ww - 1),     cx1 = min(max(x0 + 1, 0), Ww - 1);
        int i00 = cy0 * Ww + cx0, i01 = cy0 * Ww + cx1;
        int i10 = cy1 * Ww + cx0, i11 = cy1 * Ww + cx1;
        w00 = (vy0 && vx0) ? w00 * m : 0.f;
        w01 = (vy0 && vx1) ? w01 * m : 0.f;
        w10 = (vy1 && vx0) ? w10 * m : 0.f;
        w11 = (vy1 && vx1) ? w11 * m : 0.f;

        #pragma unroll
        for (int i = 0; i < 24; ++i) {
            const float* qp = qc + (size_t)i * HW;
            float val = w00 * qp[i00] + w01 * qp[i01] + w10 * qp[i10] + w11 * qp[i11];
            const float* wr = &ws[i * 9 + t];
            #pragma unroll
            for (int o = 0; o < 24; ++o) acc[o] += val * wr[o * 216];
        }
    }
    #pragma unroll
    for (int o = 0; o < 24; ++o)
        Y[((size_t)b * Cc + g * CG + o) * HW + p] = acc[o];
}

// ---------------------------------------------------------------------------
// row L2 norms for q (inside QKV buffer) and k
// ---------------------------------------------------------------------------
__global__ void rownorm_kernel(const float* __restrict__ QKV,
                               const float* __restrict__ Kb,
                               float* __restrict__ QN,
                               float* __restrict__ KN)
{
    int row   = blockIdx.x;
    int which = row / (Bn * Cc);
    row %= (Bn * Cc);
    int b = row / Cc, c = row % Cc;
    const float* src = which ? (Kb + ((size_t)b * Cc + c) * HW)
                             : (QKV + ((size_t)b * C2 + c) * HW);
    float s = 0.f;
    for (int n = threadIdx.x; n < HW; n += 256) {
        float v = src[n];
        s += v * v;
    }
    __shared__ float sm[256];
    sm[threadIdx.x] = s;
    __syncthreads();
    for (int d = 128; d > 0; d >>= 1) {
        if (threadIdx.x < d) sm[threadIdx.x] += sm[threadIdx.x + d];
        __syncthreads();
    }
    if (threadIdx.x == 0) {
        float nrm = fmaxf(sqrtf(sm[0]), 1e-12f);
        (which ? KN : QN)[b * Cc + c] = nrm;
    }
}

// ---------------------------------------------------------------------------
// attention logits + softmax.  block = (b, h, i); computes row i of 24x24.
// ---------------------------------------------------------------------------
__global__ void attn_kernel(const float* __restrict__ QKV,
                            const float* __restrict__ Kb,
                            const float* __restrict__ QN,
                            const float* __restrict__ KN,
                            const float* __restrict__ TEMP,
                            float* __restrict__ ATTN)
{
    int blk = blockIdx.x;
    int b = blk / (NH * HD);
    int h = (blk / HD) % NH;
    int i = blk % HD;
    const float* qrow  = QKV + ((size_t)b * C2 + h * HD + i) * HW;
    const float* krows = Kb  + ((size_t)b * Cc + h * HD) * HW;

    float acc[HD] = {};
    for (int n = threadIdx.x; n < HW; n += 256) {
        float qv = qrow[n];
        #pragma unroll
        for (int j = 0; j < HD; ++j)
            acc[j] += qv * krows[(size_t)j * HW + n];
    }
    __shared__ float red[HD];
    if (threadIdx.x < HD) red[threadIdx.x] = 0.f;
    __syncthreads();
    int lane = threadIdx.x & 31;
    #pragma unroll
    for (int j = 0; j < HD; ++j) {
        float v = acc[j];
        for (int o = 16; o > 0; o >>= 1) v += __shfl_down_sync(0xffffffffu, v, o);
        if (lane == 0) atomicAdd(&red[j], v);
    }
    __syncthreads();
    if (threadIdx.x == 0) {
        float qn = QN[b * Cc + h * HD + i];
        float tp = TEMP[h];
        float s[HD];
        float mx = -1e30f;
        #pragma unroll
        for (int j = 0; j < HD; ++j) {
            s[j] = red[j] / (qn * KN[b * Cc + h * HD + j]) * tp;
            mx = fmaxf(mx, s[j]);
        }
        float sum = 0.f;
        #pragma unroll
        for (int j = 0; j < HD; ++j) { s[j] = expf(s[j] - mx); sum += s[j]; }
        float inv = 1.f / sum;
        #pragma unroll
        for (int j = 0; j < HD; ++j)
            ATTN[(((size_t)b * NH + h) * HD + i) * HD + j] = s[j] * inv;
    }
}

// out = attn @ v ;  v = QKV channels 192..383
__global__ void attnv_kernel(const float* __restrict__ ATTN,
                             const float* __restrict__ QKV,
                             float* __restrict__ AO)
{
    int h = blockIdx.y, b = blockIdx.z;
    int n = blockIdx.x * 256 + threadIdx.x;
    __shared__ float a_s[HD * HD];
    for (int e = threadIdx.x; e < HD * HD; e += 256)
        a_s[e] = ATTN[((size_t)b * NH + h) * HD * HD + e];
    __syncthreads();
    const float* vb = QKV + ((size_t)b * C2 + Cc + h * HD) * HW;
    float acc[HD] = {};
    #pragma unroll
    for (int j = 0; j < HD; ++j) {
        float vv = vb[(size_t)j * HW + n];
        #pragma unroll
        for (int i = 0; i < HD; ++i) acc[i] += a_s[i * HD + j] * vv;
    }
    #pragma unroll
    for (int i = 0; i < HD; ++i)
        AO[((size_t)b * Cc + h * HD + i) * HW + n] = acc[i];
}

// ---------------------------------------------------------------------------
// launcher
// ---------------------------------------------------------------------------
extern "C" void kernel_launch(void* const* d_in, const int* in_sizes, int n_in,
                              void* d_out, int out_size)
{
    const float* x           = (const float*)d_in[0];
    const float* y           = (const float*)d_in[1];
    const float* temperature = (const float*)d_in[2];
    const float* qkv_w       = (const float*)d_in[3];
    const float* qkv_conv_w  = (const float*)d_in[4];
    const float* proj_w      = (const float*)d_in[5];
    const float* k2_w        = (const float*)d_in[6];
    const float* k3_w        = (const float*)d_in[7];
    const float* k4_w        = (const float*)d_in[8];
    const float* deform_w    = (const float*)d_in[9];
    const float* deform_b    = (const float*)d_in[10];
    const float* pw_w        = (const float*)d_in[11];
    const float* pw_b        = (const float*)d_in[12];
    float* out = (float*)d_out;

    float* S = nullptr;
    cudaGetSymbolAddress((void**)&S, g_scratch);
    float* QKV1 = S + OFF_QKV1;
    float* QKV  = S + OFF_QKV;
    float* CAT  = S + OFF_CAT;
    float* SIG  = S + OFF_SIG;
    float* SC   = S + OFF_SC;
    float* POOL = S + OFF_POOL;
    float* K2   = S + OFF_K2;
    float* OFFb = S + OFF_OFF;
    float* FEAT = S + OFF_FEAT;
    float* Kb   = S + OFF_K;
    float* AO   = S + OFF_AO;
    float* QN   = S + OFF_QN;
    float* KN   = S + OFF_KN;
    float* ATTN = S + OFF_ATTN;

    const int NE = Bn * C2 * HW;

    // 1) qkv 1x1: 384 x 192 x 9216
    conv_mma<1, 4><<<dim3(HW / 128, C2 / 128, Bn), 256>>>(
        qkv_w, x, QKV1, nullptr, nullptr, C2, Cc, Hh, Ww, Hh, Ww, 0, 0);
    // 2) grouped 3x3 (groups=192)
    dwconv_kernel<<<(NE + 255) / 256, 256>>>(QKV1, qkv_conv_w, QKV);
    // 3) cat = [q ; y]
    cat_kernel<<<(NE + 255) / 256, 256>>>(QKV, y, CAT);
    // 4) avg pool 2x2
    pool_kernel<<<(Bn * C2 * 48 * 48 + 255) / 256, 256>>>(CAT, POOL);
    // 5) k2 conv 3x3 pad=0 : 48x48 -> 46x46
    conv_mma<3, 4><<<dim3((46 * 46 + 127) / 128, C2 / 128, Bn), 256>>>(
        k2_w, POOL, K2, nullptr, nullptr, C2, C2, 48, 48, 46, 46, 0, 0);
    // 6) sig = sigmoid(cat + upsample(k2))
    sig_kernel<<<(NE + 255) / 256, 256>>>(CAT, K2, SIG);
    // 7) sc = conv3x3(cat, k3, pad=1) * sig
    conv_mma<3, 4><<<dim3(HW / 128, C2 / 128, Bn), 256>>>(
        k3_w, CAT, SC, nullptr, SIG, C2, C2, Hh, Ww, Hh, Ww, 1, 0);
    // 8) offset = conv3x3(sc, k4, pad=1), M=18 (BM=32 variant)
    conv_mma<3, 1><<<dim3(HW / 128, 1, Bn), 256>>>(
        k4_w, SC, OFFb, nullptr, nullptr, 18, C2, Hh, Ww, Hh, Ww, 1, 0);
    // 9) deformable conv -> feat
    deform_kernel<<<dim3(HW / 128, Gg, Bn), 128>>>(QKV, OFFb, deform_w, deform_b, FEAT);
    // 10) k = 1x1(relu(feat)) + pw_b
    conv_mma<1, 4><<<dim3(HW / 128, (Cc + 127) / 128, Bn), 256>>>(
        pw_w, FEAT, Kb, pw_b, nullptr, Cc, Cc, Hh, Ww, Hh, Ww, 0, 1);
    // 11) row norms for q, k
    rownorm_kernel<<<2 * Bn * Cc, 256>>>(QKV, Kb, QN, KN);
    // 12) attention logits + softmax (24x24 per head)
    attn_kernel<<<Bn * NH * HD, 256>>>(QKV, Kb, QN, KN, temperature, ATTN);
    // 13) out = attn @ v
    attnv_kernel<<<dim3(HW / 256, NH, Bn), 256>>>(ATTN, QKV, AO);
    // 14) final 1x1 proj -> d_out
    conv_mma<1, 4><<<dim3(HW / 128, (Cc + 127) / 128, Bn), 256>>>(
        proj_w, AO, out, nullptr, nullptr, Cc, Cc, Hh, Ww, Hh, Ww, 0, 0);
}